// round 1
// baseline (speedup 1.0000x reference)
#include <cuda_runtime.h>
#include <math.h>

// Problem constants (fixed shapes for this dataset)
#define MAXN 100000
#define MAXE 3200000

// ---------------- scratch (static device globals; no runtime allocation) ----
__device__ int   g_cursor[MAXN];        // degree counts, then running cursors
__device__ int   g_rowptr[MAXN + 1];    // CSR row pointers (by dst)
__device__ int   g_col[MAXE];           // CSR column = src node of each in-edge
__device__ float g_z[4][MAXN * 64];     // z0..z3 feature buffers
__device__ float g_u[MAXN * 64];        // fc pre-BN buffer
__device__ float g_stats[256];          // [0:64) sum, [64:128) sumsq, [128:192) scale, [192:256) shift

__device__ __forceinline__ float lrelu(float x) { return x >= 0.f ? x : 0.01f * x; }

// ---------------- CSR build ------------------------------------------------
__global__ void k_zero_deg(int n) {
    int i = blockIdx.x * blockDim.x + threadIdx.x;
    if (i < n) g_cursor[i] = 0;
}

__global__ void k_zero_stats() {
    int i = threadIdx.x;
    if (i < 128) g_stats[i] = 0.f;
}

__global__ void k_hist(const int* __restrict__ dst, int e) {
    int stride = gridDim.x * blockDim.x;
    for (int i = blockIdx.x * blockDim.x + threadIdx.x; i < e; i += stride)
        atomicAdd(&g_cursor[dst[i]], 1);
}

// Single-block chunked exclusive scan of g_cursor[0..n) -> g_rowptr; also
// re-initializes g_cursor to the row starts (used as fill cursors).
__global__ void k_scan(int n) {
    __shared__ int sh[1024];
    __shared__ int carry;
    int tid = threadIdx.x;
    if (tid == 0) carry = 0;
    __syncthreads();
    for (int base = 0; base < n; base += 1024) {
        int i = base + tid;
        int v = (i < n) ? g_cursor[i] : 0;
        sh[tid] = v;
        __syncthreads();
        #pragma unroll
        for (int off = 1; off < 1024; off <<= 1) {
            int t = (tid >= off) ? sh[tid - off] : 0;
            __syncthreads();
            sh[tid] += t;
            __syncthreads();
        }
        int c = carry;              // stable: carry rewritten only after next barrier
        int excl = sh[tid] - v;
        if (i < n) { g_rowptr[i] = c + excl; g_cursor[i] = c + excl; }
        int tot = sh[1023];
        __syncthreads();
        if (tid == 0) carry = c + tot;
        __syncthreads();
    }
    if (tid == 0) g_rowptr[n] = carry;
}

__global__ void k_fill(const int* __restrict__ src, const int* __restrict__ dst, int e) {
    int stride = gridDim.x * blockDim.x;
    for (int i = blockIdx.x * blockDim.x + threadIdx.x; i < e; i += stride) {
        int p = atomicAdd(&g_cursor[dst[i]], 1);
        g_col[p] = src[i];
    }
}

// ---------------- embedding lookup ----------------------------------------
__global__ void k_embed(const int* __restrict__ deg, const float* __restrict__ emb, int n) {
    int i = blockIdx.x * blockDim.x + threadIdx.x;
    if (i >= n * 32) return;
    int node = i >> 5, j = i & 31;
    ((float2*)g_z[0])[i] = ((const float2*)emb)[deg[node] * 32 + j];
}

// ---------------- fused GIN layer: gather-sum + 2x GEMV + stats ------------
__global__ void __launch_bounds__(256) k_layer(
    const float* __restrict__ W1, const float* __restrict__ b1,
    const float* __restrict__ W2, const float* __restrict__ b2,
    const float* __restrict__ epsArr, int l, int n)
{
    __shared__ float2 sW1[2048];   // 64x64 as [k][lane-pair]
    __shared__ float2 sW2[2048];
    __shared__ float2 sb1[32];
    __shared__ float2 sb2[32];
    __shared__ float  sm[8][64];
    __shared__ float  sh1[8][64];
    __shared__ float  bstat[128];

    int tid = threadIdx.x;
    {
        const float2* w1v = (const float2*)(W1 + l * 4096);
        const float2* w2v = (const float2*)(W2 + l * 4096);
        for (int i = tid; i < 2048; i += 256) { sW1[i] = w1v[i]; sW2[i] = w2v[i]; }
        if (tid < 32) {
            sb1[tid] = ((const float2*)(b1 + l * 64))[tid];
            sb2[tid] = ((const float2*)(b2 + l * 64))[tid];
        }
        if (tid < 128) bstat[tid] = 0.f;
    }
    __syncthreads();

    float ep = 1.0f + epsArr[l];
    const float2* __restrict__ x2 = (const float2*)g_z[l];
    float2* o2 = (float2*)g_z[l + 1];
    int w = tid >> 5, lane = tid & 31;
    float ssx = 0.f, ssy = 0.f, sqx = 0.f, sqy = 0.f;
    int nwarps = (gridDim.x * 256) >> 5;

    for (int node = (blockIdx.x * 256 + tid) >> 5; node < n; node += nwarps) {
        int rs = g_rowptr[node], re = g_rowptr[node + 1];
        float2 xv = x2[node * 32 + lane];
        // 4 accumulator pairs to expose MLP on the gather chain
        float a0x = ep * xv.x, a0y = ep * xv.y;
        float a1x = 0.f, a1y = 0.f, a2x = 0.f, a2y = 0.f, a3x = 0.f, a3y = 0.f;
        int b = rs;
        for (; b + 32 <= re; b += 32) {
            int j = g_col[b + lane];
            #pragma unroll
            for (int t = 0; t < 32; t += 4) {
                int j0 = __shfl_sync(0xffffffffu, j, t);
                int j1 = __shfl_sync(0xffffffffu, j, t + 1);
                int j2 = __shfl_sync(0xffffffffu, j, t + 2);
                int j3 = __shfl_sync(0xffffffffu, j, t + 3);
                float2 v0 = x2[j0 * 32 + lane];
                float2 v1 = x2[j1 * 32 + lane];
                float2 v2 = x2[j2 * 32 + lane];
                float2 v3 = x2[j3 * 32 + lane];
                a0x += v0.x; a0y += v0.y;
                a1x += v1.x; a1y += v1.y;
                a2x += v2.x; a2y += v2.y;
                a3x += v3.x; a3y += v3.y;
            }
        }
        if (b < re) {
            int rem = re - b;
            int j = (lane < rem) ? g_col[b + lane] : 0;
            for (int t = 0; t < rem; t++) {
                int jj = __shfl_sync(0xffffffffu, j, t);
                float2 v = x2[jj * 32 + lane];
                a0x += v.x; a0y += v.y;
            }
        }
        float mx = (a0x + a1x) + (a2x + a3x);
        float my = (a0y + a1y) + (a2y + a3y);
        sm[w][2 * lane] = mx; sm[w][2 * lane + 1] = my;
        __syncwarp();

        // GEMV1: h = lrelu(m @ W1 + b1)
        float2 h = sb1[lane];
        const float4* mv = (const float4*)sm[w];
        #pragma unroll
        for (int k4 = 0; k4 < 16; k4++) {
            float4 m4 = mv[k4];
            float2 w0 = sW1[(4 * k4 + 0) * 32 + lane];
            float2 w1 = sW1[(4 * k4 + 1) * 32 + lane];
            float2 w2 = sW1[(4 * k4 + 2) * 32 + lane];
            float2 w3 = sW1[(4 * k4 + 3) * 32 + lane];
            h.x = fmaf(m4.x, w0.x, h.x); h.y = fmaf(m4.x, w0.y, h.y);
            h.x = fmaf(m4.y, w1.x, h.x); h.y = fmaf(m4.y, w1.y, h.y);
            h.x = fmaf(m4.z, w2.x, h.x); h.y = fmaf(m4.z, w2.y, h.y);
            h.x = fmaf(m4.w, w3.x, h.x); h.y = fmaf(m4.w, w3.y, h.y);
        }
        h.x = lrelu(h.x); h.y = lrelu(h.y);
        sh1[w][2 * lane] = h.x; sh1[w][2 * lane + 1] = h.y;
        __syncwarp();

        // GEMV2: o = h1 @ W2 + b2 (pre-BN)
        float2 o = sb2[lane];
        const float4* hv = (const float4*)sh1[w];
        #pragma unroll
        for (int k4 = 0; k4 < 16; k4++) {
            float4 m4 = hv[k4];
            float2 w0 = sW2[(4 * k4 + 0) * 32 + lane];
            float2 w1 = sW2[(4 * k4 + 1) * 32 + lane];
            float2 w2 = sW2[(4 * k4 + 2) * 32 + lane];
            float2 w3 = sW2[(4 * k4 + 3) * 32 + lane];
            o.x = fmaf(m4.x, w0.x, o.x); o.y = fmaf(m4.x, w0.y, o.y);
            o.x = fmaf(m4.y, w1.x, o.x); o.y = fmaf(m4.y, w1.y, o.y);
            o.x = fmaf(m4.z, w2.x, o.x); o.y = fmaf(m4.z, w2.y, o.y);
            o.x = fmaf(m4.w, w3.x, o.x); o.y = fmaf(m4.w, w3.y, o.y);
        }
        o2[node * 32 + lane] = o;
        ssx += o.x; ssy += o.y; sqx += o.x * o.x; sqy += o.y * o.y;
        __syncwarp();
    }

    // two-level stat reduction: shared atomics, then 128 global atomics/block
    atomicAdd(&bstat[2 * lane], ssx);
    atomicAdd(&bstat[2 * lane + 1], ssy);
    atomicAdd(&bstat[64 + 2 * lane], sqx);
    atomicAdd(&bstat[64 + 2 * lane + 1], sqy);
    __syncthreads();
    if (tid < 128) atomicAdd(&g_stats[tid], bstat[tid]);
}

// ---------------- BN param computation (1 block) ---------------------------
__global__ void k_bnparams(const float* __restrict__ g, const float* __restrict__ b, int n) {
    int i = threadIdx.x;
    if (i < 64) {
        float inv = 1.0f / (float)n;
        float mean = g_stats[i] * inv;
        float var = g_stats[64 + i] * inv - mean * mean;
        float sc = g[i] * rsqrtf(var + 1e-5f);
        g_stats[128 + i] = sc;
        g_stats[192 + i] = b[i] - sc * mean;
    }
}

// ---------------- in-place BN + leaky on z[lz] ------------------------------
__global__ void k_bnapply(int lz, int n) {
    int i = blockIdx.x * blockDim.x + threadIdx.x;
    if (i >= n * 32) return;
    int c = (i & 31) * 2;
    float2* z2 = (float2*)g_z[lz];
    float2 v = z2[i];
    v.x = lrelu(g_stats[128 + c] * v.x + g_stats[192 + c]);
    v.y = lrelu(g_stats[128 + c + 1] * v.y + g_stats[192 + c + 1]);
    z2[i] = v;
}

// ---------------- FC layer 1, in two 128-row chunks -------------------------
__global__ void __launch_bounds__(256) k_fc(
    const float* __restrict__ fcW1, const float* __restrict__ fcb1, int chunk, int n)
{
    __shared__ float2 sW[4096];    // 128x64 weights = 32 KB
    __shared__ float  sx[8][128];
    __shared__ float2 sb[32];
    __shared__ float  bstat[128];
    int tid = threadIdx.x;
    const float2* wv = (const float2*)(fcW1 + chunk * 128 * 64);
    for (int i = tid; i < 4096; i += 256) sW[i] = wv[i];
    if (tid < 32) sb[tid] = (chunk == 0) ? ((const float2*)fcb1)[tid] : make_float2(0.f, 0.f);
    if (tid < 128) bstat[tid] = 0.f;
    __syncthreads();

    const float2* za = (const float2*)g_z[2 * chunk];
    const float2* zb = (const float2*)g_z[2 * chunk + 1];
    float2* u2 = (float2*)g_u;
    int w = tid >> 5, lane = tid & 31;
    float ssx = 0.f, ssy = 0.f, sqx = 0.f, sqy = 0.f;
    int nwarps = (gridDim.x * 256) >> 5;

    for (int node = (blockIdx.x * 256 + tid) >> 5; node < n; node += nwarps) {
        ((float2*)sx[w])[lane] = za[node * 32 + lane];
        ((float2*)sx[w])[32 + lane] = zb[node * 32 + lane];
        __syncwarp();
        float2 u = (chunk == 0) ? sb[lane] : u2[node * 32 + lane];
        const float4* xv = (const float4*)sx[w];
        #pragma unroll
        for (int k4 = 0; k4 < 32; k4++) {
            float4 m4 = xv[k4];
            float2 w0 = sW[(4 * k4 + 0) * 32 + lane];
            float2 w1 = sW[(4 * k4 + 1) * 32 + lane];
            float2 w2 = sW[(4 * k4 + 2) * 32 + lane];
            float2 w3 = sW[(4 * k4 + 3) * 32 + lane];
            u.x = fmaf(m4.x, w0.x, u.x); u.y = fmaf(m4.x, w0.y, u.y);
            u.x = fmaf(m4.y, w1.x, u.x); u.y = fmaf(m4.y, w1.y, u.y);
            u.x = fmaf(m4.z, w2.x, u.x); u.y = fmaf(m4.z, w2.y, u.y);
            u.x = fmaf(m4.w, w3.x, u.x); u.y = fmaf(m4.w, w3.y, u.y);
        }
        u2[node * 32 + lane] = u;
        if (chunk == 1) { ssx += u.x; ssy += u.y; sqx += u.x * u.x; sqy += u.y * u.y; }
        __syncwarp();
    }

    if (chunk == 1) {
        atomicAdd(&bstat[2 * lane], ssx);
        atomicAdd(&bstat[2 * lane + 1], ssy);
        atomicAdd(&bstat[64 + 2 * lane], sqx);
        atomicAdd(&bstat[64 + 2 * lane + 1], sqy);
        __syncthreads();
        if (tid < 128) atomicAdd(&g_stats[tid], bstat[tid]);
    }
}

// ---------------- head: BN + leaky + dot(fc_W2) + sigmoid -------------------
__global__ void k_head(const float* __restrict__ fcW2, const float* __restrict__ fcb2,
                       float* __restrict__ out, int n) {
    int gt = blockIdx.x * blockDim.x + threadIdx.x;
    int node = gt >> 5, lane = gt & 31;
    if (node >= n) return;
    float2 u = ((const float2*)g_u)[node * 32 + lane];
    int c = 2 * lane;
    float y0 = lrelu(g_stats[128 + c] * u.x + g_stats[192 + c]);
    float y1 = lrelu(g_stats[128 + c + 1] * u.y + g_stats[192 + c + 1]);
    float p = y0 * fcW2[c] + y1 * fcW2[c + 1];
    #pragma unroll
    for (int o = 16; o > 0; o >>= 1) p += __shfl_xor_sync(0xffffffffu, p, o);
    if (lane == 0) out[node] = 1.0f / (1.0f + expf(-(p + fcb2[0])));
}

// ---------------- launch ----------------------------------------------------
extern "C" void kernel_launch(void* const* d_in, const int* in_sizes, int n_in,
                              void* d_out, int out_size) {
    const int*   node_deg = (const int*)d_in[0];
    const int*   edge_idx = (const int*)d_in[1];
    const float* embed    = (const float*)d_in[2];
    const float* eps      = (const float*)d_in[3];
    const float* W1       = (const float*)d_in[4];
    const float* b1       = (const float*)d_in[5];
    const float* W2       = (const float*)d_in[6];
    const float* b2       = (const float*)d_in[7];
    const float* bn_g     = (const float*)d_in[8];
    const float* bn_b     = (const float*)d_in[9];
    const float* fcW1     = (const float*)d_in[10];
    const float* fcb1     = (const float*)d_in[11];
    const float* fc_bn_g  = (const float*)d_in[12];
    const float* fc_bn_b  = (const float*)d_in[13];
    const float* fcW2     = (const float*)d_in[14];
    const float* fcb2     = (const float*)d_in[15];

    int n = in_sizes[0];
    int e = in_sizes[1] / 2;
    const int* src = edge_idx;
    const int* dst = edge_idx + e;

    int elemBlocks = (n * 32 + 255) / 256;

    // CSR build (reused across all 3 layers)
    k_zero_deg<<<(n + 255) / 256, 256>>>(n);
    k_hist<<<1024, 256>>>(dst, e);
    k_scan<<<1, 1024>>>(n);
    k_fill<<<1024, 256>>>(src, dst, e);

    // z0 = embedding lookup
    k_embed<<<elemBlocks, 256>>>(node_deg, embed, n);

    // 3 GIN layers
    for (int l = 0; l < 3; l++) {
        k_zero_stats<<<1, 128>>>();
        k_layer<<<912, 256>>>(W1, b1, W2, b2, eps, l, n);
        k_bnparams<<<1, 64>>>(bn_g + l * 64, bn_b + l * 64, n);
        k_bnapply<<<elemBlocks, 256>>>(l + 1, n);
    }

    // FC head
    k_zero_stats<<<1, 128>>>();
    k_fc<<<912, 256>>>(fcW1, fcb1, 0, n);
    k_fc<<<912, 256>>>(fcW1, fcb1, 1, n);
    k_bnparams<<<1, 64>>>(fc_bn_g, fc_bn_b, n);
    k_head<<<elemBlocks, 256>>>(fcW2, fcb2, (float*)d_out, n);
}